// round 1
// baseline (speedup 1.0000x reference)
#include <cuda_runtime.h>
#include <math.h>
#include <stdint.h>

#define Bsz  128
#define Tlen 256
#define HID  512
#define GATE 1536
#define OUTN 64
#define MTOT (Bsz * Tlen)   // 32768

typedef unsigned long long ull;

// -------- static device scratch (no allocations allowed) --------
__device__ float    g_xg[(size_t)MTOT * GATE];    // 201 MB: gate preactivations (reused per layer)
__device__ float    g_hseq[(size_t)MTOT * HID];   // 67 MB: layer-0 outputs (input to layer-1 GEMM)
__device__ float    g_h[2][Bsz * HID];            // double-buffered hidden state
__device__ unsigned g_ctr[2];                     // grid barrier counters (one per layer)

// -------- packed fp32x2 helpers (Blackwell FFMA2) --------
__device__ __forceinline__ ull splat2(float a) {
    ull d; asm("mov.b64 %0, {%1, %1};" : "=l"(d) : "f"(a)); return d;
}
__device__ __forceinline__ ull pack2(float lo, float hi) {
    ull d; asm("mov.b64 %0, {%1, %2};" : "=l"(d) : "f"(lo), "f"(hi)); return d;
}
__device__ __forceinline__ ull fma2(ull a, ull b, ull c) {
    ull d; asm("fma.rn.f32x2 %0, %1, %2, %3;" : "=l"(d) : "l"(a), "l"(b), "l"(c)); return d;
}
__device__ __forceinline__ float2 unpack2(ull v) {
    float2 r; asm("mov.b64 {%0, %1}, %2;" : "=f"(r.x), "=f"(r.y) : "l"(v)); return r;
}

// ============================================================
// init: zero the grid-barrier counters (h zeroing happens inside recur)
// ============================================================
__global__ void init_k() {
    if (threadIdx.x < 2) g_ctr[threadIdx.x] = 0u;
}

// ============================================================
// xg GEMM: g_xg[m, g] = sum_k A[m,k] * W[g,k] + bias[g]
// A is [MTOT, K] row-major (x for layer 0, g_hseq for layer 1), W is [1536, K].
// 64x64 tile, Ktile=16, 256 threads, 4x4 per thread via FFMA2.
// ============================================================
__global__ __launch_bounds__(256) void gemm_xg_k(
    const float* __restrict__ Ain, const float* __restrict__ W,
    const float* __restrict__ bias, int K, int use_hseq)
{
    const float* __restrict__ A = use_hseq ? (const float*)g_hseq : Ain;
    __shared__ float As[16][68];
    __shared__ float Bs[16][68];

    int tid = threadIdx.x;
    int tx = tid & 15, ty = tid >> 4;
    int lr = tid >> 2, lc = tid & 3;
    int m0 = blockIdx.y << 6;
    int n0 = blockIdx.x << 6;

    const float4* Ap = (const float4*)(A + (size_t)(m0 + lr) * K) + lc;
    const float4* Bp = (const float4*)(W + (size_t)(n0 + lr) * K) + lc;

    ull acc[4][2];
#pragma unroll
    for (int i = 0; i < 4; i++) { acc[i][0] = 0ULL; acc[i][1] = 0ULL; }

    int nch = K >> 4;
    for (int c = 0; c < nch; c++) {
        float4 av = __ldg(Ap + c * 4);
        float4 bv = __ldg(Bp + c * 4);
        __syncthreads();
        int kb = lc << 2;
        As[kb + 0][lr] = av.x; As[kb + 1][lr] = av.y;
        As[kb + 2][lr] = av.z; As[kb + 3][lr] = av.w;
        Bs[kb + 0][lr] = bv.x; Bs[kb + 1][lr] = bv.y;
        Bs[kb + 2][lr] = bv.z; Bs[kb + 3][lr] = bv.w;
        __syncthreads();
#pragma unroll
        for (int kk = 0; kk < 16; kk++) {
            float4 a = *(const float4*)&As[kk][ty << 2];
            const ull* bp = (const ull*)&Bs[kk][tx << 2];
            ull b01 = bp[0], b23 = bp[1];
            ull a0 = splat2(a.x), a1 = splat2(a.y), a2 = splat2(a.z), a3 = splat2(a.w);
            acc[0][0] = fma2(a0, b01, acc[0][0]); acc[0][1] = fma2(a0, b23, acc[0][1]);
            acc[1][0] = fma2(a1, b01, acc[1][0]); acc[1][1] = fma2(a1, b23, acc[1][1]);
            acc[2][0] = fma2(a2, b01, acc[2][0]); acc[2][1] = fma2(a2, b23, acc[2][1]);
            acc[3][0] = fma2(a3, b01, acc[3][0]); acc[3][1] = fma2(a3, b23, acc[3][1]);
        }
    }

    float4 bb = __ldg((const float4*)(bias + n0) + tx);
#pragma unroll
    for (int i = 0; i < 4; i++) {
        float2 c01 = unpack2(acc[i][0]);
        float2 c23 = unpack2(acc[i][1]);
        float4 o;
        o.x = c01.x + bb.x; o.y = c01.y + bb.y;
        o.z = c23.x + bb.z; o.w = c23.y + bb.w;
        *((float4*)(g_xg + (size_t)(m0 + (ty << 2) + i) * GATE + n0) + tx) = o;
    }
}

// ============================================================
// Persistent recurrent kernel: one launch runs all 256 steps of one layer.
// Grid: 128 blocks = 4 batch-tiles(32) x 32 j-tiles(16 j each -> 48 gate rows).
// W_hh slice (48 rows x 512, j-pair packed for FFMA2) lives in SMEM for all steps.
// One atomic grid barrier per step; h double-buffered in global (L2-resident).
// ============================================================
#define WS_BYTES  (3 * 8 * 256 * 16)            // 96 KB packed weights
#define HS_FLOATS (512 * 33)                    // padded transposed h tile
#define RECUR_SMEM (WS_BYTES + HS_FLOATS * 4)   // 98304 + 67584 = 165888 B

__global__ __launch_bounds__(256, 1) void recur_k(
    const float* __restrict__ Whh, const float* __restrict__ bhh, int layer)
{
    extern __shared__ char smraw[];
    ulonglong2* ws2 = (ulonglong2*)smraw;                 // [3][8][256] j-pair packed
    float* hs = (float*)(smraw + WS_BYTES);               // hs[k][b], stride 33

    int tid = threadIdx.x;
    int bt = blockIdx.x >> 5;   // batch tile 0..3
    int jt = blockIdx.x & 31;   // j tile 0..31
    int bg0 = bt << 5;

    // ---- one-time: pack W_hh rows {jt*16+jj, +8} for gates r,z,n into SMEM ----
    for (int i = tid; i < 3 * 8 * 256; i += 256) {
        int k2 = i & 255;
        int jj2 = (i >> 8) & 7;
        int g = i >> 11;
        int r0 = g * HID + (jt << 4) + jj2;
        const float2* p0 = (const float2*)(Whh + (size_t)r0 * HID);
        const float2* p1 = (const float2*)(Whh + (size_t)(r0 + 8) * HID);
        float2 a = __ldg(p0 + k2);
        float2 bq = __ldg(p1 + k2);
        ulonglong2 w;
        w.x = pack2(a.x, bq.x);   // (w_j0[2k], w_j1[2k])
        w.y = pack2(a.y, bq.y);   // (w_j0[2k+1], w_j1[2k+1])
        ws2[i] = w;
    }

    int b  = tid & 31;
    int jj = tid >> 5;
    int jg0 = (jt << 4) + jj;
    int jg1 = jg0 + 8;
    int bg = bg0 + b;

    ull bias_r = pack2(__ldg(bhh + jg0),            __ldg(bhh + jg1));
    ull bias_z = pack2(__ldg(bhh + HID + jg0),      __ldg(bhh + HID + jg1));
    ull bias_n = pack2(__ldg(bhh + 2 * HID + jg0),  __ldg(bhh + 2 * HID + jg1));

    unsigned* ctr = &g_ctr[layer];

    // ---- phase 0: zero this block's slice of h buffer 0 ----
    for (int i = tid; i < 512; i += 256) {
        int bb2 = i & 31, jl = i >> 5;
        g_h[0][(bg0 + bb2) * HID + (jt << 4) + jl] = 0.0f;
    }
    __threadfence();
    __syncthreads();
    if (tid == 0) {
        atomicAdd(ctr, 1u);
        while (*((volatile unsigned*)ctr) < 128u) {}
    }
    __syncthreads();

    const ulonglong2* wr = ws2 + ((0 * 8 + jj) << 8);
    const ulonglong2* wz = ws2 + ((1 * 8 + jj) << 8);
    const ulonglong2* wn = ws2 + ((2 * 8 + jj) << 8);

    for (int t = 0; t < Tlen; t++) {
        int rb = t & 1, wb = rb ^ 1;

        // ---- load h tile [32 x 512] -> transposed hs[k][b] (coalesced + 33-pad) ----
        const float4* hsrc = (const float4*)(g_h[rb] + (size_t)bg0 * HID);
        for (int i = tid; i < 32 * 128; i += 256) {
            int row = i >> 7, kq = i & 127;
            float4 v = __ldcg(hsrc + row * 128 + kq);
            int kb = kq << 2;
            hs[(kb + 0) * 33 + row] = v.x;
            hs[(kb + 1) * 33 + row] = v.y;
            hs[(kb + 2) * 33 + row] = v.z;
            hs[(kb + 3) * 33 + row] = v.w;
        }
        __syncthreads();

        // ---- hg = h @ Whh^T for gate rows (r,z,n) x (jg0,jg1), FFMA2 packed ----
        ull accr = bias_r, accz = bias_z, accn = bias_n;
        const float* hp = hs + b;
#pragma unroll 8
        for (int k2 = 0; k2 < 256; k2++) {
            ull h0 = splat2(hp[0]);
            ull h1 = splat2(hp[33]);
            hp += 66;
            ulonglong2 w = wr[k2];
            accr = fma2(w.x, h0, accr); accr = fma2(w.y, h1, accr);
            w = wz[k2];
            accz = fma2(w.x, h0, accz); accz = fma2(w.y, h1, accz);
            w = wn[k2];
            accn = fma2(w.x, h0, accn); accn = fma2(w.y, h1, accn);
        }
        float2 hr = unpack2(accr), hz = unpack2(accz), hn = unpack2(accn);

        // ---- gates + state update ----
        size_t row = ((size_t)bg * Tlen + t) * GATE;
        float xr0 = __ldg(g_xg + row + jg0);
        float xz0 = __ldg(g_xg + row + HID + jg0);
        float xn0 = __ldg(g_xg + row + 2 * HID + jg0);
        float xr1 = __ldg(g_xg + row + jg1);
        float xz1 = __ldg(g_xg + row + HID + jg1);
        float xn1 = __ldg(g_xg + row + 2 * HID + jg1);

        float r0v = 1.0f / (1.0f + __expf(-(xr0 + hr.x)));
        float z0v = 1.0f / (1.0f + __expf(-(xz0 + hz.x)));
        float n0v = tanhf(xn0 + r0v * hn.x);
        float ho0 = hs[jg0 * 33 + b];
        float hnew0 = (1.0f - z0v) * n0v + z0v * ho0;

        float r1v = 1.0f / (1.0f + __expf(-(xr1 + hr.y)));
        float z1v = 1.0f / (1.0f + __expf(-(xz1 + hz.y)));
        float n1v = tanhf(xn1 + r1v * hn.y);
        float ho1 = hs[jg1 * 33 + b];
        float hnew1 = (1.0f - z1v) * n1v + z1v * ho1;

        g_h[wb][bg * HID + jg0] = hnew0;
        g_h[wb][bg * HID + jg1] = hnew1;
        if (layer == 0) {
            size_t srow = ((size_t)bg * Tlen + t) * HID;
            g_hseq[srow + jg0] = hnew0;
            g_hseq[srow + jg1] = hnew1;
        }

        // ---- grid barrier (release: fence + atomic arrive; acquire: spin) ----
        __threadfence();
        __syncthreads();
        if (tid == 0) {
            atomicAdd(ctr, 1u);
            unsigned target = 128u * (unsigned)(t + 2);
            while (*((volatile unsigned*)ctr) < target) {}
        }
        __syncthreads();
    }
}

// ============================================================
// output: yhat[b,o] = h_final[b,:] . W_out[o,:] + b_out[o]
// Final h of layer 1 recurrence lives in g_h[0] (Tlen even).
// ============================================================
__global__ __launch_bounds__(64) void out_k(
    const float* __restrict__ Wout, const float* __restrict__ bout,
    float* __restrict__ out)
{
    __shared__ float hrow[HID];
    int bg = blockIdx.x, tid = threadIdx.x;
    for (int i = tid; i < HID; i += 64) hrow[i] = g_h[0][bg * HID + i];
    __syncthreads();
    float acc = __ldg(bout + tid);
    const float* w = Wout + (size_t)tid * HID;
#pragma unroll 8
    for (int j = 0; j < HID; j++) acc += hrow[j] * __ldg(w + j);
    out[bg * OUTN + tid] = acc;
}

// ============================================================
extern "C" void kernel_launch(void* const* d_in, const int* in_sizes, int n_in,
                              void* d_out, int out_size)
{
    const float* x     = (const float*)d_in[0];
    const float* W_ih0 = (const float*)d_in[1];
    const float* W_hh0 = (const float*)d_in[2];
    const float* b_ih0 = (const float*)d_in[3];
    const float* b_hh0 = (const float*)d_in[4];
    const float* W_ih1 = (const float*)d_in[5];
    const float* W_hh1 = (const float*)d_in[6];
    const float* b_ih1 = (const float*)d_in[7];
    const float* b_hh1 = (const float*)d_in[8];
    const float* W_out = (const float*)d_in[9];
    const float* b_out = (const float*)d_in[10];
    float* out = (float*)d_out;

    cudaFuncSetAttribute(recur_k, cudaFuncAttributeMaxDynamicSharedMemorySize,
                         RECUR_SMEM);

    init_k<<<1, 32>>>();

    // layer 0
    gemm_xg_k<<<dim3(GATE / 64, MTOT / 64), 256>>>(x, W_ih0, b_ih0, 256, 0);
    recur_k<<<128, 256, RECUR_SMEM>>>(W_hh0, b_hh0, 0);

    // layer 1
    gemm_xg_k<<<dim3(GATE / 64, MTOT / 64), 256>>>(nullptr, W_ih1, b_ih1, 512, 1);
    recur_k<<<128, 256, RECUR_SMEM>>>(W_hh1, b_hh1, 1);

    // output projection
    out_k<<<Bsz, OUTN>>>(W_out, b_out, out);
}